// round 15
// baseline (speedup 1.0000x reference)
#include <cuda_runtime.h>
#include <cuda_bf16.h>
#include <cstdint>

static constexpr int Bn = 4096;
static constexpr int Dn = 512;
static constexpr int Hn = 16;
static constexpr long DD = (long)Dn * Dn;

// ---------------------------------------------------------------------------
// Device scratch
// ---------------------------------------------------------------------------
__device__ float g_T[48 * Dn * Dn];  // fp32 K-split partials (s1: 32 banks, s4: 16)
__device__ float g_lam[Bn];
__device__ float g_cnt;

#define BF16_SCRATCH(name, n) __device__ __align__(16) __nv_bfloat16 name[n]
BF16_SCRATCH(sWk_h, 512 * 8192);  BF16_SCRATCH(sWk_l, 512 * 8192);
BF16_SCRATCH(sWkT_h, 8192 * 512); BF16_SCRATCH(sWkT_l, 8192 * 512);
BF16_SCRATCH(sMemT_h, 512 * 8192);BF16_SCRATCH(sMemT_l, 512 * 8192);
BF16_SCRATCH(sWvT_h, 8192 * 512); BF16_SCRATCH(sWvT_l, 8192 * 512);
BF16_SCRATCH(sWoT_h, 512 * 512);  BF16_SCRATCH(sWoT_l, 512 * 512);
BF16_SCRATCH(sZq_h, 4096 * 512);  BF16_SCRATCH(sZq_l, 4096 * 512);
BF16_SCRATCH(sZsT_h, 512 * 4096); BF16_SCRATCH(sZsT_l, 512 * 4096);
BF16_SCRATCH(sZvT_h, 512 * 4096); BF16_SCRATCH(sZvT_l, 512 * 4096);
BF16_SCRATCH(sA1_h, 512 * 512);   BF16_SCRATCH(sA1_l, 512 * 512);
BF16_SCRATCH(sA2T_h, 512 * 512);  BF16_SCRATCH(sA2T_l, 512 * 512);
BF16_SCRATCH(sST_h, 512 * 512);   BF16_SCRATCH(sST_l, 512 * 512);
BF16_SCRATCH(sT_h, 16 * 512 * 512); BF16_SCRATCH(sT_l, 16 * 512 * 512);

// ---------------------------------------------------------------------------
// helpers
// ---------------------------------------------------------------------------
__device__ __forceinline__ uint32_t smem_u32(const void* p) {
    uint32_t a;
    asm("{ .reg .u64 t; cvta.to.shared.u64 t, %1; cvt.u32.u64 %0, t; }"
        : "=r"(a) : "l"(p));
    return a;
}
__device__ __forceinline__ void ldsm4(uint32_t* r, uint32_t addr) {
    asm volatile("ldmatrix.sync.aligned.m8n8.x4.shared.b16 {%0,%1,%2,%3}, [%4];"
                 : "=r"(r[0]), "=r"(r[1]), "=r"(r[2]), "=r"(r[3]) : "r"(addr));
}
__device__ __forceinline__ void mma16816(float* c, const uint32_t* a, const uint32_t* b) {
    asm volatile(
        "mma.sync.aligned.m16n8k16.row.col.f32.bf16.bf16.f32 "
        "{%0,%1,%2,%3}, {%4,%5,%6,%7}, {%8,%9}, {%0,%1,%2,%3};"
        : "+f"(c[0]), "+f"(c[1]), "+f"(c[2]), "+f"(c[3])
        : "r"(a[0]), "r"(a[1]), "r"(a[2]), "r"(a[3]), "r"(b[0]), "r"(b[1]));
}
__device__ __forceinline__ void cp16(uint32_t dst, const void* src) {
    asm volatile("cp.async.cg.shared.global [%0], [%1], 16;" :: "r"(dst), "l"(src));
}
__device__ __forceinline__ void cp_commit() { asm volatile("cp.async.commit_group;"); }
__device__ __forceinline__ void cp_wait1() { asm volatile("cp.async.wait_group 1;"); }
__device__ __forceinline__ void cp_wait0() { asm volatile("cp.async.wait_group 0;"); }

__device__ __forceinline__ void split1(float v, __nv_bfloat16& h, __nv_bfloat16& l) {
    h = __float2bfloat16(v);
    l = __float2bfloat16(v - __bfloat162float(h));
}
__device__ __forceinline__ uint32_t pack2(float a, float b, float& ra, float& rb) {
    __nv_bfloat162 p{__float2bfloat16(a), __float2bfloat16(b)};
    ra = a - __bfloat162float(p.x);
    rb = b - __bfloat162float(p.y);
    return *(uint32_t*)&p;
}
__device__ __forceinline__ uint32_t pack2lo(float a, float b) {
    __nv_bfloat162 p{__float2bfloat16(a), __float2bfloat16(b)};
    return *(uint32_t*)&p;
}

// ---------------------------------------------------------------------------
// lam prep
// ---------------------------------------------------------------------------
__global__ void prep_lam_kernel(const float* __restrict__ conf) {
    int t = threadIdx.x;
    float local = 0.f;
    for (int i = t; i < Bn; i += 256) {
        float lam = fminf(fmaxf(1.0f - conf[i], 0.f), 1.f);
        float m = (lam > 0.3f) ? 1.f : 0.f;
        g_lam[i] = lam * m;
        local += m;
    }
#pragma unroll
    for (int o = 16; o > 0; o >>= 1) local += __shfl_down_sync(0xffffffffu, local, o);
    __shared__ float ws[8];
    if ((t & 31) == 0) ws[t >> 5] = local;
    __syncthreads();
    if (t == 0) {
        float s = 0.f;
#pragma unroll
        for (int w = 0; w < 8; w++) s += ws[w];
        g_cnt = s;
    }
}

// sum K-split partials -> bf16 hi/lo (direct layout)
__global__ void reduce_split(const float* __restrict__ part, __nv_bfloat16* __restrict__ hi,
                             __nv_bfloat16* __restrict__ lo, int nElem, int nPart) {
    int i = blockIdx.x * blockDim.x + threadIdx.x;
    if (i < nElem) {
        float s = 0.f;
        for (int p = 0; p < nPart; p++) s += part[(long)p * nElem + i];
        __nv_bfloat16 h, l;
        split1(s, h, l);
        hi[i] = h; lo[i] = l;
    }
}

// sum K-split partials (512x512) -> TRANSPOSED bf16 hi/lo
__global__ void reduce_splitT(const float* __restrict__ part, __nv_bfloat16* __restrict__ hi,
                              __nv_bfloat16* __restrict__ lo, int nPart) {
    __shared__ float t[32][33];
    int c0 = blockIdx.x * 32, r0 = blockIdx.y * 32;
    int tx = threadIdx.x, ty = threadIdx.y;  // 32x8
#pragma unroll
    for (int i = 0; i < 32; i += 8) {
        long o = (long)(r0 + ty + i) * 512 + c0 + tx;
        float s = 0.f;
        for (int p = 0; p < nPart; p++) s += part[(long)p * DD + o];
        t[ty + i][tx] = s;
    }
    __syncthreads();
#pragma unroll
    for (int i = 0; i < 32; i += 8) {
        float v = t[tx][ty + i];
        long o = (long)(c0 + ty + i) * 512 + r0 + tx;
        __nv_bfloat16 h, l;
        split1(v, h, l);
        hi[o] = h; lo[o] = l;
    }
}

// ---------------------------------------------------------------------------
// Vectorized conversions: 64x64 tiles, float4 loads, uint2 (4 x bf16) stores.
// ---------------------------------------------------------------------------
__global__ void transSplit4(const float* __restrict__ src, __nv_bfloat16* __restrict__ hi,
                            __nv_bfloat16* __restrict__ lo, int R, int C) {
    __shared__ float t[64][65];
    int c0 = blockIdx.x * 64, r0 = blockIdx.y * 64;
    int tid = threadIdx.x;
    int f4 = tid & 15, row4 = tid >> 4;
#pragma unroll
    for (int j = 0; j < 4; j++) {
        int row = row4 + 16 * j;
        float4 v = *(const float4*)(src + (long)(r0 + row) * C + c0 + f4 * 4);
        t[row][f4 * 4] = v.x; t[row][f4 * 4 + 1] = v.y;
        t[row][f4 * 4 + 2] = v.z; t[row][f4 * 4 + 3] = v.w;
    }
    __syncthreads();
    int rg = tid & 15, cl = tid >> 4;
#pragma unroll
    for (int p = 0; p < 4; p++) {
        int c = cl + 16 * p;
        float v0 = t[4 * rg][c], v1 = t[4 * rg + 1][c];
        float v2 = t[4 * rg + 2][c], v3 = t[4 * rg + 3][c];
        float l0, l1, l2, l3;
        uint2 uh{pack2(v0, v1, l0, l1), pack2(v2, v3, l2, l3)};
        uint2 ul{pack2lo(l0, l1), pack2lo(l2, l3)};
        long o = (long)(c0 + c) * R + r0 + 4 * rg;
        *(uint2*)(hi + o) = uh;
        *(uint2*)(lo + o) = ul;
    }
}

// Wk (512x8192): one read -> direct split + transposed split
__global__ void convWk4(const float* __restrict__ src,
                        __nv_bfloat16* __restrict__ dh, __nv_bfloat16* __restrict__ dl,
                        __nv_bfloat16* __restrict__ th, __nv_bfloat16* __restrict__ tl) {
    __shared__ float t[64][65];
    const int R = 512, C = 8192;
    int c0 = blockIdx.x * 64, r0 = blockIdx.y * 64;
    int tid = threadIdx.x;
    int f4 = tid & 15, row4 = tid >> 4;
#pragma unroll
    for (int j = 0; j < 4; j++) {
        int row = row4 + 16 * j;
        long o = (long)(r0 + row) * C + c0 + f4 * 4;
        float4 v = *(const float4*)(src + o);
        t[row][f4 * 4] = v.x; t[row][f4 * 4 + 1] = v.y;
        t[row][f4 * 4 + 2] = v.z; t[row][f4 * 4 + 3] = v.w;
        float l0, l1, l2, l3;
        uint2 uh{pack2(v.x, v.y, l0, l1), pack2(v.z, v.w, l2, l3)};
        uint2 ul{pack2lo(l0, l1), pack2lo(l2, l3)};
        *(uint2*)(dh + o) = uh;
        *(uint2*)(dl + o) = ul;
    }
    __syncthreads();
    int rg = tid & 15, cl = tid >> 4;
#pragma unroll
    for (int p = 0; p < 4; p++) {
        int c = cl + 16 * p;
        float v0 = t[4 * rg][c], v1 = t[4 * rg + 1][c];
        float v2 = t[4 * rg + 2][c], v3 = t[4 * rg + 3][c];
        float l0, l1, l2, l3;
        uint2 uh{pack2(v0, v1, l0, l1), pack2(v2, v3, l2, l3)};
        uint2 ul{pack2lo(l0, l1), pack2lo(l2, l3)};
        long o = (long)(c0 + c) * R + r0 + 4 * rg;
        *(uint2*)(th + o) = uh;
        *(uint2*)(tl + o) = ul;
    }
}

// zq direct + zs (lam-scaled, transposed) + zv (transposed). 4096x512.
__global__ void convZ4(const float* __restrict__ zq, const float* __restrict__ zs,
                       const float* __restrict__ zv,
                       __nv_bfloat16* __restrict__ qh, __nv_bfloat16* __restrict__ ql,
                       __nv_bfloat16* __restrict__ sh, __nv_bfloat16* __restrict__ sl,
                       __nv_bfloat16* __restrict__ vh, __nv_bfloat16* __restrict__ vl) {
    __shared__ float ts[64][65], tv[64][65];
    const int R = 4096, C = 512;
    int c0 = blockIdx.x * 64, r0 = blockIdx.y * 64;
    int tid = threadIdx.x;
    int f4 = tid & 15, row4 = tid >> 4;
#pragma unroll
    for (int j = 0; j < 4; j++) {
        int row = row4 + 16 * j;
        int r = r0 + row;
        long o = (long)r * C + c0 + f4 * 4;
        float lam = g_lam[r];
        float4 q = *(const float4*)(zq + o);
        float l0, l1, l2, l3;
        uint2 uh{pack2(q.x, q.y, l0, l1), pack2(q.z, q.w, l2, l3)};
        uint2 ul{pack2lo(l0, l1), pack2lo(l2, l3)};
        *(uint2*)(qh + o) = uh;
        *(uint2*)(ql + o) = ul;
        float4 s = *(const float4*)(zs + o);
        ts[row][f4 * 4] = s.x * lam; ts[row][f4 * 4 + 1] = s.y * lam;
        ts[row][f4 * 4 + 2] = s.z * lam; ts[row][f4 * 4 + 3] = s.w * lam;
        float4 v = *(const float4*)(zv + o);
        tv[row][f4 * 4] = v.x; tv[row][f4 * 4 + 1] = v.y;
        tv[row][f4 * 4 + 2] = v.z; tv[row][f4 * 4 + 3] = v.w;
    }
    __syncthreads();
    int rg = tid & 15, cl = tid >> 4;
#pragma unroll
    for (int p = 0; p < 4; p++) {
        int c = cl + 16 * p;
        long o = (long)(c0 + c) * R + r0 + 4 * rg;
        float l0, l1, l2, l3;
        {
            float v0 = ts[4 * rg][c], v1 = ts[4 * rg + 1][c];
            float v2 = ts[4 * rg + 2][c], v3 = ts[4 * rg + 3][c];
            uint2 uh{pack2(v0, v1, l0, l1), pack2(v2, v3, l2, l3)};
            uint2 ul{pack2lo(l0, l1), pack2lo(l2, l3)};
            *(uint2*)(sh + o) = uh;
            *(uint2*)(sl + o) = ul;
        }
        {
            float v0 = tv[4 * rg][c], v1 = tv[4 * rg + 1][c];
            float v2 = tv[4 * rg + 2][c], v3 = tv[4 * rg + 3][c];
            uint2 uh{pack2(v0, v1, l0, l1), pack2(v2, v3, l2, l3)};
            uint2 ul{pack2lo(l0, l1), pack2lo(l2, l3)};
            *(uint2*)(vh + o) = uh;
            *(uint2*)(vl + o) = ul;
        }
    }
}

// ---------------------------------------------------------------------------
// Dual-op HMMA bf16-split GEMM (R12 config: 256 thr, 8 warps 4x2, warp 32x64,
// K-chunk 32, ROWB 80, GSMEM 80KB, 2 CTAs/SM).
// ---------------------------------------------------------------------------
static constexpr int ROWB = 80;
static constexpr int TILEB = 128 * ROWB;   // 10240
static constexpr int BUFB = 4 * TILEB;     // 40960
static constexpr int GSMEM = 2 * BUFB;     // 81920

struct GOp {
    const __nv_bfloat16 *Ah, *Al, *Bh, *Bl;
    float* C;
    __nv_bfloat16 *Chi, *Clo;
    const float* addC;
    int K, ldA, ldB, ldC, ksplit, epi, gx, gy, ctaCount;
    long sA, sB, sC, sAdd, sSplit;
    float alpha;
};

__global__ __launch_bounds__(256, 2) void mma_dual(GOp op0, GOp op1) {
    extern __shared__ __align__(16) char sm[];
    const uint32_t sbase = smem_u32(sm);
    const int tid = threadIdx.x;
    const int wid = tid >> 5, lane = tid & 31;
    const int warpM = wid & 3, warpN = wid >> 2;

    const bool second = (int)blockIdx.x >= op0.ctaCount;
    const GOp op = second ? op1 : op0;
    int idx = (int)blockIdx.x - (second ? op0.ctaCount : 0);
    const int x = idx % op.gx;
    int rem = idx / op.gx;
    const int y = rem % op.gy;
    const int bz = rem / op.gy;
    const int batch = bz / op.ksplit;
    const int split = bz - batch * op.ksplit;

    const __nv_bfloat16* Ah = op.Ah + (long)batch * op.sA;
    const __nv_bfloat16* Al = op.Al + (long)batch * op.sA;
    const __nv_bfloat16* Bh = op.Bh + (long)batch * op.sB;
    const __nv_bfloat16* Bl = op.Bl + (long)batch * op.sB;
    const int kLen = op.K / op.ksplit;
    const long k0 = (long)split * kLen;
    const int rowA = y * 128;
    const int colB = x * 128;
    const int ldA = op.ldA, ldB = op.ldB, ldC = op.ldC;

    const int nCk = kLen >> 5;   // 32-wide K chunks
    const int lr = tid >> 2;     // 0..63 (+i*64)
    const int lc = tid & 3;      // 16B chunk within 64B row

    float acc[2][8][4] = {};

    const uint32_t aAddrOff =
        (uint32_t)(warpM * 32 + (lane & 15)) * ROWB + (lane >> 4) * 16;
    const uint32_t bAddrOff =
        (uint32_t)(warpN * 64 + ((lane >> 4) << 3) + (lane & 7)) * ROWB +
        ((lane >> 3) & 1) * 16;

    auto issue_load = [&](int ck, int buf) {
        const long kb = k0 + (long)ck * 32;
        uint32_t base = sbase + buf * BUFB;
#pragma unroll
        for (int i = 0; i < 2; i++) {
            int r = lr + i * 64;
            uint32_t so = (uint32_t)r * ROWB + lc * 16;
            long ao = (long)(rowA + r) * ldA + kb + lc * 8;
            long bo = (long)(colB + r) * ldB + kb + lc * 8;
            cp16(base + so, Ah + ao);
            cp16(base + TILEB + so, Al + ao);
            cp16(base + 2 * TILEB + so, Bh + bo);
            cp16(base + 3 * TILEB + so, Bl + bo);
        }
    };

    issue_load(0, 0);
    cp_commit();

    for (int c = 0; c < nCk; c++) {
        const int buf = c & 1;
        if (c + 1 < nCk) {
            issue_load(c + 1, (c + 1) & 1);
            cp_commit();
            cp_wait1();
        } else {
            cp_wait0();
        }
        __syncthreads();

        uint32_t aH = sbase + buf * BUFB;
        uint32_t aL = aH + TILEB;
        uint32_t bH = aL + TILEB;
        uint32_t bL = bH + TILEB;
#pragma unroll
        for (int ks = 0; ks < 2; ks++) {
            uint32_t afh[2][4], afl[2][4];
#pragma unroll
            for (int mt = 0; mt < 2; mt++) {
                ldsm4(afh[mt], aH + aAddrOff + mt * (16 * ROWB) + ks * 32);
                ldsm4(afl[mt], aL + aAddrOff + mt * (16 * ROWB) + ks * 32);
            }
            uint32_t bfh[8][2], bfl[8][2];
#pragma unroll
            for (int q = 0; q < 4; q++) {
                uint32_t r4[4];
                ldsm4(r4, bH + bAddrOff + q * (16 * ROWB) + ks * 32);
                bfh[2 * q][0] = r4[0]; bfh[2 * q][1] = r4[1];
                bfh[2 * q + 1][0] = r4[2]; bfh[2 * q + 1][1] = r4[3];
                ldsm4(r4, bL + bAddrOff + q * (16 * ROWB) + ks * 32);
                bfl[2 * q][0] = r4[0]; bfl[2 * q][1] = r4[1];
                bfl[2 * q + 1][0] = r4[2]; bfl[2 * q + 1][1] = r4[3];
            }
#pragma unroll
            for (int mt = 0; mt < 2; mt++)
#pragma unroll
                for (int nt = 0; nt < 8; nt++) {
                    mma16816(acc[mt][nt], afh[mt], bfh[nt]);
                    mma16816(acc[mt][nt], afh[mt], bfl[nt]);
                    mma16816(acc[mt][nt], afl[mt], bfh[nt]);
                }
        }
        __syncthreads();
    }

    // epilogue (uniform per CTA)
    const int epi = op.epi;
    float scale = (epi == 2) ? (1.f / (g_cnt + 1e-6f)) : op.alpha;
    float* C = op.C;
    __nv_bfloat16* Chi = op.Chi;
    __nv_bfloat16* Clo = op.Clo;
    const float* addP = op.addC;
    if (epi == 1) { Chi += (long)batch * op.sC; Clo += (long)batch * op.sC; }
    else C += (long)batch * op.sC + (long)split * op.sSplit;
    if (epi == 2) addP += (long)batch * op.sAdd;

#pragma unroll
    for (int mt = 0; mt < 2; mt++) {
        int mrow = rowA + warpM * 32 + mt * 16 + (lane >> 2);
#pragma unroll
        for (int nt = 0; nt < 8; nt++) {
            int ncol = colB + warpN * 64 + nt * 8 + 2 * (lane & 3);
            long i0 = (long)mrow * ldC + ncol;
            long i1 = (long)(mrow + 8) * ldC + ncol;
            float2 v0{acc[mt][nt][0] * scale, acc[mt][nt][1] * scale};
            float2 v1{acc[mt][nt][2] * scale, acc[mt][nt][3] * scale};
            if (epi == 1) {
                __nv_bfloat16 h0, l0, h1, l1;
                split1(v0.x, h0, l0); split1(v0.y, h1, l1);
                *(__nv_bfloat162*)(Chi + i0) = __nv_bfloat162{h0, h1};
                *(__nv_bfloat162*)(Clo + i0) = __nv_bfloat162{l0, l1};
                split1(v1.x, h0, l0); split1(v1.y, h1, l1);
                *(__nv_bfloat162*)(Chi + i1) = __nv_bfloat162{h0, h1};
                *(__nv_bfloat162*)(Clo + i1) = __nv_bfloat162{l0, l1};
            } else {
                if (epi == 2) {
                    v0.x += addP[i0]; v0.y += addP[i0 + 1];
                    v1.x += addP[i1]; v1.y += addP[i1 + 1];
                }
                *(float2*)(C + i0) = v0;
                *(float2*)(C + i1) = v1;
            }
        }
    }
}

// ---------------------------------------------------------------------------
extern "C" void kernel_launch(void* const* d_in, const int* in_sizes, int n_in,
                              void* d_out, int out_size) {
    const float* zq = (const float*)d_in[0];
    const float* zs = (const float*)d_in[1];
    const float* zv = (const float*)d_in[2];
    const float* cf = (const float*)d_in[3];
    const float* Wk = (const float*)d_in[4];
    const float* Wv = (const float*)d_in[5];
    const float* Wo = (const float*)d_in[6];
    const float* mem = (const float*)d_in[7];

    float* out = (float*)d_out;
    float* vret = out;
    float* newmem = out + (long)Bn * Dn;

    float* pT;
    cudaGetSymbolAddress((void**)&pT, g_T);

#define SYM(p, s) __nv_bfloat16* p; cudaGetSymbolAddress((void**)&p, s)
    SYM(pWk_h, sWk_h);   SYM(pWk_l, sWk_l);
    SYM(pWkT_h, sWkT_h); SYM(pWkT_l, sWkT_l);
    SYM(pMemT_h, sMemT_h); SYM(pMemT_l, sMemT_l);
    SYM(pWvT_h, sWvT_h); SYM(pWvT_l, sWvT_l);
    SYM(pWoT_h, sWoT_h); SYM(pWoT_l, sWoT_l);
    SYM(pZq_h, sZq_h);   SYM(pZq_l, sZq_l);
    SYM(pZsT_h, sZsT_h); SYM(pZsT_l, sZsT_l);
    SYM(pZvT_h, sZvT_h); SYM(pZvT_l, sZvT_l);
    SYM(pA1_h, sA1_h);   SYM(pA1_l, sA1_l);
    SYM(pA2T_h, sA2T_h); SYM(pA2T_l, sA2T_l);
    SYM(pST_h, sST_h);   SYM(pST_l, sST_l);
    SYM(pT_h, sT_h);     SYM(pT_l, sT_l);
#undef SYM

    cudaFuncSetAttribute(mma_dual, cudaFuncAttributeMaxDynamicSharedMemorySize, GSMEM);

    prep_lam_kernel<<<1, 256>>>(cf);

    // conversions (vectorized)
    convWk4<<<dim3(128, 8), 256>>>(Wk, pWk_h, pWk_l, pWkT_h, pWkT_l);
    transSplit4<<<dim3(8, 128), 256>>>(mem, pMemT_h, pMemT_l, 8192, 512);
    transSplit4<<<dim3(128, 8), 256>>>(Wv, pWvT_h, pWvT_l, 512, 8192);
    transSplit4<<<dim3(8, 8), 256>>>(Wo, pWoT_h, pWoT_l, 512, 512);
    convZ4<<<dim3(8, 64), 256>>>(zq, zs, zv, pZq_h, pZq_l, pZsT_h, pZsT_l, pZvT_h, pZvT_l);

    auto mkop = [](const __nv_bfloat16* Ah, const __nv_bfloat16* Al,
                   const __nv_bfloat16* Bh, const __nv_bfloat16* Bl,
                   float* C, __nv_bfloat16* Chi, __nv_bfloat16* Clo, const float* addC,
                   int K, int ldA, int ldB, int ldC, int ksplit, int epi,
                   int gx, int gy, int gz, long sA, long sB, long sC, long sAdd,
                   long sSplit, float alpha) {
        GOp o;
        o.Ah = Ah; o.Al = Al; o.Bh = Bh; o.Bl = Bl;
        o.C = C; o.Chi = Chi; o.Clo = Clo; o.addC = addC;
        o.K = K; o.ldA = ldA; o.ldB = ldB; o.ldC = ldC;
        o.ksplit = ksplit; o.epi = epi; o.gx = gx; o.gy = gy;
        o.ctaCount = gx * gy * gz;
        o.sA = sA; o.sB = sB; o.sC = sC; o.sAdd = sAdd; o.sSplit = sSplit;
        o.alpha = alpha;
        return o;
    };

    // G1 (uniform 8-chunk CTAs, 768 total):
    // s1: A1 partials = Wk @ memT (K=8192, ksplit 32 -> 512 CTAs) -> banks 0..31
    GOp s1 = mkop(pWk_h, pWk_l, pMemT_h, pMemT_l, pT, nullptr, nullptr, nullptr,
                  8192, 8192, 8192, 512, 32, 0, 4, 4, 32, 0, 0, 0, 0, DD, 1.f);
    // s4: S partials = zsT @ zvT (K=4096, ksplit 16 -> 256 CTAs) -> banks 32..47
    GOp s4 = mkop(pZsT_h, pZsT_l, pZvT_h, pZvT_l, pT + 32 * DD, nullptr, nullptr, nullptr,
                  4096, 4096, 4096, 512, 16, 0, 4, 4, 16, 0, 0, 0, 0, DD, 1.f);
    mma_dual<<<s1.ctaCount + s4.ctaCount, 256, GSMEM>>>(s1, s4);

    reduce_split<<<(Dn * Dn + 255) / 256, 256>>>(pT, pA1_h, pA1_l, Dn * Dn, 32);
    reduce_splitT<<<dim3(16, 16), dim3(32, 8)>>>(pT + 32 * DD, pST_h, pST_l, 16);

    // G2: s5 (T_h, bf16 epilogue) + s2 (A2 partials, ksplit 4 -> banks 0..3)
    GOp s5 = mkop(pWkT_h, pWkT_l, pST_h, pST_l, nullptr, pT_h, pT_l, nullptr,
                  512, 512, 512, 512, 1, 1, 4, 4, 16, DD, 0, DD, 0, 0, 1.f);
    GOp s2 = mkop(pA1_h, pA1_l, pWoT_h, pWoT_l, pT, nullptr, nullptr, nullptr,
                  512, 512, 512, 512, 4, 0, 4, 4, 4, 0, 0, 0, 0, DD, 1.f / Hn);
    mma_dual<<<s5.ctaCount + s2.ctaCount, 256, GSMEM>>>(s5, s2);

    reduce_splitT<<<dim3(16, 16), dim3(32, 8)>>>(pT, pA2T_h, pA2T_l, 4);

    // G3: s6 (new_mem) + s3 (v_ret)
    GOp s6 = mkop(pT_h, pT_l, pWvT_h, pWvT_l, newmem, nullptr, nullptr, mem,
                  512, 512, 512, 512, 1, 2, 4, 4, 16, DD, DD, DD, DD, 0, 1.f);
    GOp s3 = mkop(pZq_h, pZq_l, pA2T_h, pA2T_l, vret, nullptr, nullptr, nullptr,
                  512, 512, 512, 512, 1, 0, 4, 32, 1, 0, 0, 0, 0, 0, 1.f);
    mma_dual<<<s6.ctaCount + s3.ctaCount, 256, GSMEM>>>(s6, s3);
}

// round 16
// speedup vs baseline: 1.1007x; 1.1007x over previous
#include <cuda_runtime.h>
#include <cuda_bf16.h>
#include <cstdint>

static constexpr int Bn = 4096;
static constexpr int Dn = 512;
static constexpr int Hn = 16;
static constexpr long DD = (long)Dn * Dn;

// ---------------------------------------------------------------------------
// Device scratch
// ---------------------------------------------------------------------------
__device__ float g_T[2 * 8 * Dn * Dn];  // fp32 K-split partials (two banks of 8)
__device__ float g_lam[Bn];
__device__ float g_cnt;

#define BF16_SCRATCH(name, n) __device__ __align__(16) __nv_bfloat16 name[n]
BF16_SCRATCH(sWk_h, 512 * 8192);  BF16_SCRATCH(sWk_l, 512 * 8192);
BF16_SCRATCH(sWkT_h, 8192 * 512); BF16_SCRATCH(sWkT_l, 8192 * 512);
BF16_SCRATCH(sMemT_h, 512 * 8192);BF16_SCRATCH(sMemT_l, 512 * 8192);
BF16_SCRATCH(sWvT_h, 8192 * 512); BF16_SCRATCH(sWvT_l, 8192 * 512);
BF16_SCRATCH(sWoT_h, 512 * 512);  BF16_SCRATCH(sWoT_l, 512 * 512);
BF16_SCRATCH(sZq_h, 4096 * 512);  BF16_SCRATCH(sZq_l, 4096 * 512);
BF16_SCRATCH(sZsT_h, 512 * 4096); BF16_SCRATCH(sZsT_l, 512 * 4096);
BF16_SCRATCH(sZvT_h, 512 * 4096); BF16_SCRATCH(sZvT_l, 512 * 4096);
BF16_SCRATCH(sA1_h, 512 * 512);   BF16_SCRATCH(sA1_l, 512 * 512);
BF16_SCRATCH(sA2T_h, 512 * 512);  BF16_SCRATCH(sA2T_l, 512 * 512);
BF16_SCRATCH(sST_h, 512 * 512);   BF16_SCRATCH(sST_l, 512 * 512);
BF16_SCRATCH(sT_h, 16 * 512 * 512); BF16_SCRATCH(sT_l, 16 * 512 * 512);

// ---------------------------------------------------------------------------
// helpers
// ---------------------------------------------------------------------------
__device__ __forceinline__ uint32_t smem_u32(const void* p) {
    uint32_t a;
    asm("{ .reg .u64 t; cvta.to.shared.u64 t, %1; cvt.u32.u64 %0, t; }"
        : "=r"(a) : "l"(p));
    return a;
}
__device__ __forceinline__ void ldsm4(uint32_t* r, uint32_t addr) {
    asm volatile("ldmatrix.sync.aligned.m8n8.x4.shared.b16 {%0,%1,%2,%3}, [%4];"
                 : "=r"(r[0]), "=r"(r[1]), "=r"(r[2]), "=r"(r[3]) : "r"(addr));
}
__device__ __forceinline__ void mma16816(float* c, const uint32_t* a, const uint32_t* b) {
    asm volatile(
        "mma.sync.aligned.m16n8k16.row.col.f32.bf16.bf16.f32 "
        "{%0,%1,%2,%3}, {%4,%5,%6,%7}, {%8,%9}, {%0,%1,%2,%3};"
        : "+f"(c[0]), "+f"(c[1]), "+f"(c[2]), "+f"(c[3])
        : "r"(a[0]), "r"(a[1]), "r"(a[2]), "r"(a[3]), "r"(b[0]), "r"(b[1]));
}
__device__ __forceinline__ void cp16(uint32_t dst, const void* src) {
    asm volatile("cp.async.cg.shared.global [%0], [%1], 16;" :: "r"(dst), "l"(src));
}
__device__ __forceinline__ void cp_commit() { asm volatile("cp.async.commit_group;"); }
__device__ __forceinline__ void cp_wait1() { asm volatile("cp.async.wait_group 1;"); }
__device__ __forceinline__ void cp_wait0() { asm volatile("cp.async.wait_group 0;"); }

__device__ __forceinline__ void split1(float v, __nv_bfloat16& h, __nv_bfloat16& l) {
    h = __float2bfloat16(v);
    l = __float2bfloat16(v - __bfloat162float(h));
}
__device__ __forceinline__ uint32_t pack2(float a, float b, float& ra, float& rb) {
    __nv_bfloat162 p{__float2bfloat16(a), __float2bfloat16(b)};
    ra = a - __bfloat162float(p.x);
    rb = b - __bfloat162float(p.y);
    return *(uint32_t*)&p;
}
__device__ __forceinline__ uint32_t pack2lo(float a, float b) {
    __nv_bfloat162 p{__float2bfloat16(a), __float2bfloat16(b)};
    return *(uint32_t*)&p;
}

// ---------------------------------------------------------------------------
// lam prep
// ---------------------------------------------------------------------------
__global__ void prep_lam_kernel(const float* __restrict__ conf) {
    int t = threadIdx.x;
    float local = 0.f;
    for (int i = t; i < Bn; i += 256) {
        float lam = fminf(fmaxf(1.0f - conf[i], 0.f), 1.f);
        float m = (lam > 0.3f) ? 1.f : 0.f;
        g_lam[i] = lam * m;
        local += m;
    }
#pragma unroll
    for (int o = 16; o > 0; o >>= 1) local += __shfl_down_sync(0xffffffffu, local, o);
    __shared__ float ws[8];
    if ((t & 31) == 0) ws[t >> 5] = local;
    __syncthreads();
    if (t == 0) {
        float s = 0.f;
#pragma unroll
        for (int w = 0; w < 8; w++) s += ws[w];
        g_cnt = s;
    }
}

// sum K-split partials -> bf16 hi/lo (direct layout)
__global__ void reduce_split(const float* __restrict__ part, __nv_bfloat16* __restrict__ hi,
                             __nv_bfloat16* __restrict__ lo, int nElem, int nPart) {
    int i = blockIdx.x * blockDim.x + threadIdx.x;
    if (i < nElem) {
        float s = 0.f;
        for (int p = 0; p < nPart; p++) s += part[(long)p * nElem + i];
        __nv_bfloat16 h, l;
        split1(s, h, l);
        hi[i] = h; lo[i] = l;
    }
}

// sum K-split partials (512x512) -> TRANSPOSED bf16 hi/lo
__global__ void reduce_splitT(const float* __restrict__ part, __nv_bfloat16* __restrict__ hi,
                              __nv_bfloat16* __restrict__ lo, int nPart) {
    __shared__ float t[32][33];
    int c0 = blockIdx.x * 32, r0 = blockIdx.y * 32;
    int tx = threadIdx.x, ty = threadIdx.y;  // 32x8
#pragma unroll
    for (int i = 0; i < 32; i += 8) {
        long o = (long)(r0 + ty + i) * 512 + c0 + tx;
        float s = 0.f;
        for (int p = 0; p < nPart; p++) s += part[(long)p * DD + o];
        t[ty + i][tx] = s;
    }
    __syncthreads();
#pragma unroll
    for (int i = 0; i < 32; i += 8) {
        float v = t[tx][ty + i];
        long o = (long)(c0 + ty + i) * 512 + r0 + tx;
        __nv_bfloat16 h, l;
        split1(v, h, l);
        hi[o] = h; lo[o] = l;
    }
}

// ---------------------------------------------------------------------------
// Vectorized conversions: 64x64 tiles, float4 loads, uint2 (4 x bf16) stores.
// ---------------------------------------------------------------------------
__global__ void transSplit4(const float* __restrict__ src, __nv_bfloat16* __restrict__ hi,
                            __nv_bfloat16* __restrict__ lo, int R, int C) {
    __shared__ float t[64][65];
    int c0 = blockIdx.x * 64, r0 = blockIdx.y * 64;
    int tid = threadIdx.x;
    int f4 = tid & 15, row4 = tid >> 4;
#pragma unroll
    for (int j = 0; j < 4; j++) {
        int row = row4 + 16 * j;
        float4 v = *(const float4*)(src + (long)(r0 + row) * C + c0 + f4 * 4);
        t[row][f4 * 4] = v.x; t[row][f4 * 4 + 1] = v.y;
        t[row][f4 * 4 + 2] = v.z; t[row][f4 * 4 + 3] = v.w;
    }
    __syncthreads();
    int rg = tid & 15, cl = tid >> 4;
#pragma unroll
    for (int p = 0; p < 4; p++) {
        int c = cl + 16 * p;
        float v0 = t[4 * rg][c], v1 = t[4 * rg + 1][c];
        float v2 = t[4 * rg + 2][c], v3 = t[4 * rg + 3][c];
        float l0, l1, l2, l3;
        uint2 uh{pack2(v0, v1, l0, l1), pack2(v2, v3, l2, l3)};
        uint2 ul{pack2lo(l0, l1), pack2lo(l2, l3)};
        long o = (long)(c0 + c) * R + r0 + 4 * rg;
        *(uint2*)(hi + o) = uh;
        *(uint2*)(lo + o) = ul;
    }
}

// Wk (512x8192): one read -> direct split + transposed split
__global__ void convWk4(const float* __restrict__ src,
                        __nv_bfloat16* __restrict__ dh, __nv_bfloat16* __restrict__ dl,
                        __nv_bfloat16* __restrict__ th, __nv_bfloat16* __restrict__ tl) {
    __shared__ float t[64][65];
    const int R = 512, C = 8192;
    int c0 = blockIdx.x * 64, r0 = blockIdx.y * 64;
    int tid = threadIdx.x;
    int f4 = tid & 15, row4 = tid >> 4;
#pragma unroll
    for (int j = 0; j < 4; j++) {
        int row = row4 + 16 * j;
        long o = (long)(r0 + row) * C + c0 + f4 * 4;
        float4 v = *(const float4*)(src + o);
        t[row][f4 * 4] = v.x; t[row][f4 * 4 + 1] = v.y;
        t[row][f4 * 4 + 2] = v.z; t[row][f4 * 4 + 3] = v.w;
        float l0, l1, l2, l3;
        uint2 uh{pack2(v.x, v.y, l0, l1), pack2(v.z, v.w, l2, l3)};
        uint2 ul{pack2lo(l0, l1), pack2lo(l2, l3)};
        *(uint2*)(dh + o) = uh;
        *(uint2*)(dl + o) = ul;
    }
    __syncthreads();
    int rg = tid & 15, cl = tid >> 4;
#pragma unroll
    for (int p = 0; p < 4; p++) {
        int c = cl + 16 * p;
        float v0 = t[4 * rg][c], v1 = t[4 * rg + 1][c];
        float v2 = t[4 * rg + 2][c], v3 = t[4 * rg + 3][c];
        float l0, l1, l2, l3;
        uint2 uh{pack2(v0, v1, l0, l1), pack2(v2, v3, l2, l3)};
        uint2 ul{pack2lo(l0, l1), pack2lo(l2, l3)};
        long o = (long)(c0 + c) * R + r0 + 4 * rg;
        *(uint2*)(th + o) = uh;
        *(uint2*)(tl + o) = ul;
    }
}

// zq direct + zs (lam-scaled, transposed) + zv (transposed). 4096x512.
__global__ void convZ4(const float* __restrict__ zq, const float* __restrict__ zs,
                       const float* __restrict__ zv,
                       __nv_bfloat16* __restrict__ qh, __nv_bfloat16* __restrict__ ql,
                       __nv_bfloat16* __restrict__ sh, __nv_bfloat16* __restrict__ sl,
                       __nv_bfloat16* __restrict__ vh, __nv_bfloat16* __restrict__ vl) {
    __shared__ float ts[64][65], tv[64][65];
    const int R = 4096, C = 512;
    int c0 = blockIdx.x * 64, r0 = blockIdx.y * 64;
    int tid = threadIdx.x;
    int f4 = tid & 15, row4 = tid >> 4;
#pragma unroll
    for (int j = 0; j < 4; j++) {
        int row = row4 + 16 * j;
        int r = r0 + row;
        long o = (long)r * C + c0 + f4 * 4;
        float lam = g_lam[r];
        float4 q = *(const float4*)(zq + o);
        float l0, l1, l2, l3;
        uint2 uh{pack2(q.x, q.y, l0, l1), pack2(q.z, q.w, l2, l3)};
        uint2 ul{pack2lo(l0, l1), pack2lo(l2, l3)};
        *(uint2*)(qh + o) = uh;
        *(uint2*)(ql + o) = ul;
        float4 s = *(const float4*)(zs + o);
        ts[row][f4 * 4] = s.x * lam; ts[row][f4 * 4 + 1] = s.y * lam;
        ts[row][f4 * 4 + 2] = s.z * lam; ts[row][f4 * 4 + 3] = s.w * lam;
        float4 v = *(const float4*)(zv + o);
        tv[row][f4 * 4] = v.x; tv[row][f4 * 4 + 1] = v.y;
        tv[row][f4 * 4 + 2] = v.z; tv[row][f4 * 4 + 3] = v.w;
    }
    __syncthreads();
    int rg = tid & 15, cl = tid >> 4;
#pragma unroll
    for (int p = 0; p < 4; p++) {
        int c = cl + 16 * p;
        long o = (long)(c0 + c) * R + r0 + 4 * rg;
        float l0, l1, l2, l3;
        {
            float v0 = ts[4 * rg][c], v1 = ts[4 * rg + 1][c];
            float v2 = ts[4 * rg + 2][c], v3 = ts[4 * rg + 3][c];
            uint2 uh{pack2(v0, v1, l0, l1), pack2(v2, v3, l2, l3)};
            uint2 ul{pack2lo(l0, l1), pack2lo(l2, l3)};
            *(uint2*)(sh + o) = uh;
            *(uint2*)(sl + o) = ul;
        }
        {
            float v0 = tv[4 * rg][c], v1 = tv[4 * rg + 1][c];
            float v2 = tv[4 * rg + 2][c], v3 = tv[4 * rg + 3][c];
            uint2 uh{pack2(v0, v1, l0, l1), pack2(v2, v3, l2, l3)};
            uint2 ul{pack2lo(l0, l1), pack2lo(l2, l3)};
            *(uint2*)(vh + o) = uh;
            *(uint2*)(vl + o) = ul;
        }
    }
}

// ---------------------------------------------------------------------------
// Dual-op HMMA bf16-split GEMM (R12 config: 256 thr, 8 warps 4x2, warp 32x64,
// K-chunk 32, ROWB 80, GSMEM 80KB, 2 CTAs/SM).
// ---------------------------------------------------------------------------
static constexpr int ROWB = 80;
static constexpr int TILEB = 128 * ROWB;   // 10240
static constexpr int BUFB = 4 * TILEB;     // 40960
static constexpr int GSMEM = 2 * BUFB;     // 81920

struct GOp {
    const __nv_bfloat16 *Ah, *Al, *Bh, *Bl;
    float* C;
    __nv_bfloat16 *Chi, *Clo;
    const float* addC;
    int K, ldA, ldB, ldC, ksplit, epi, gx, gy, ctaCount;
    long sA, sB, sC, sAdd, sSplit;
    float alpha;
};

__global__ __launch_bounds__(256, 2) void mma_dual(GOp op0, GOp op1) {
    extern __shared__ __align__(16) char sm[];
    const uint32_t sbase = smem_u32(sm);
    const int tid = threadIdx.x;
    const int wid = tid >> 5, lane = tid & 31;
    const int warpM = wid & 3, warpN = wid >> 2;

    const bool second = (int)blockIdx.x >= op0.ctaCount;
    const GOp op = second ? op1 : op0;
    int idx = (int)blockIdx.x - (second ? op0.ctaCount : 0);
    const int x = idx % op.gx;
    int rem = idx / op.gx;
    const int y = rem % op.gy;
    const int bz = rem / op.gy;
    const int batch = bz / op.ksplit;
    const int split = bz - batch * op.ksplit;

    const __nv_bfloat16* Ah = op.Ah + (long)batch * op.sA;
    const __nv_bfloat16* Al = op.Al + (long)batch * op.sA;
    const __nv_bfloat16* Bh = op.Bh + (long)batch * op.sB;
    const __nv_bfloat16* Bl = op.Bl + (long)batch * op.sB;
    const int kLen = op.K / op.ksplit;
    const long k0 = (long)split * kLen;
    const int rowA = y * 128;
    const int colB = x * 128;
    const int ldA = op.ldA, ldB = op.ldB, ldC = op.ldC;

    const int nCk = kLen >> 5;   // 32-wide K chunks
    const int lr = tid >> 2;     // 0..63 (+i*64)
    const int lc = tid & 3;      // 16B chunk within 64B row

    float acc[2][8][4] = {};

    const uint32_t aAddrOff =
        (uint32_t)(warpM * 32 + (lane & 15)) * ROWB + (lane >> 4) * 16;
    const uint32_t bAddrOff =
        (uint32_t)(warpN * 64 + ((lane >> 4) << 3) + (lane & 7)) * ROWB +
        ((lane >> 3) & 1) * 16;

    auto issue_load = [&](int ck, int buf) {
        const long kb = k0 + (long)ck * 32;
        uint32_t base = sbase + buf * BUFB;
#pragma unroll
        for (int i = 0; i < 2; i++) {
            int r = lr + i * 64;
            uint32_t so = (uint32_t)r * ROWB + lc * 16;
            long ao = (long)(rowA + r) * ldA + kb + lc * 8;
            long bo = (long)(colB + r) * ldB + kb + lc * 8;
            cp16(base + so, Ah + ao);
            cp16(base + TILEB + so, Al + ao);
            cp16(base + 2 * TILEB + so, Bh + bo);
            cp16(base + 3 * TILEB + so, Bl + bo);
        }
    };

    issue_load(0, 0);
    cp_commit();

    for (int c = 0; c < nCk; c++) {
        const int buf = c & 1;
        if (c + 1 < nCk) {
            issue_load(c + 1, (c + 1) & 1);
            cp_commit();
            cp_wait1();
        } else {
            cp_wait0();
        }
        __syncthreads();

        uint32_t aH = sbase + buf * BUFB;
        uint32_t aL = aH + TILEB;
        uint32_t bH = aL + TILEB;
        uint32_t bL = bH + TILEB;
#pragma unroll
        for (int ks = 0; ks < 2; ks++) {
            uint32_t afh[2][4], afl[2][4];
#pragma unroll
            for (int mt = 0; mt < 2; mt++) {
                ldsm4(afh[mt], aH + aAddrOff + mt * (16 * ROWB) + ks * 32);
                ldsm4(afl[mt], aL + aAddrOff + mt * (16 * ROWB) + ks * 32);
            }
            uint32_t bfh[8][2], bfl[8][2];
#pragma unroll
            for (int q = 0; q < 4; q++) {
                uint32_t r4[4];
                ldsm4(r4, bH + bAddrOff + q * (16 * ROWB) + ks * 32);
                bfh[2 * q][0] = r4[0]; bfh[2 * q][1] = r4[1];
                bfh[2 * q + 1][0] = r4[2]; bfh[2 * q + 1][1] = r4[3];
                ldsm4(r4, bL + bAddrOff + q * (16 * ROWB) + ks * 32);
                bfl[2 * q][0] = r4[0]; bfl[2 * q][1] = r4[1];
                bfl[2 * q + 1][0] = r4[2]; bfl[2 * q + 1][1] = r4[3];
            }
#pragma unroll
            for (int mt = 0; mt < 2; mt++)
#pragma unroll
                for (int nt = 0; nt < 8; nt++) {
                    mma16816(acc[mt][nt], afh[mt], bfh[nt]);
                    mma16816(acc[mt][nt], afh[mt], bfl[nt]);
                    mma16816(acc[mt][nt], afl[mt], bfh[nt]);
                }
        }
        __syncthreads();
    }

    // epilogue (uniform per CTA)
    const int epi = op.epi;
    float scale = (epi == 2) ? (1.f / (g_cnt + 1e-6f)) : op.alpha;
    float* C = op.C;
    __nv_bfloat16* Chi = op.Chi;
    __nv_bfloat16* Clo = op.Clo;
    const float* addP = op.addC;
    if (epi == 1) { Chi += (long)batch * op.sC; Clo += (long)batch * op.sC; }
    else C += (long)batch * op.sC + (long)split * op.sSplit;
    if (epi == 2) addP += (long)batch * op.sAdd;

#pragma unroll
    for (int mt = 0; mt < 2; mt++) {
        int mrow = rowA + warpM * 32 + mt * 16 + (lane >> 2);
#pragma unroll
        for (int nt = 0; nt < 8; nt++) {
            int ncol = colB + warpN * 64 + nt * 8 + 2 * (lane & 3);
            long i0 = (long)mrow * ldC + ncol;
            long i1 = (long)(mrow + 8) * ldC + ncol;
            float2 v0{acc[mt][nt][0] * scale, acc[mt][nt][1] * scale};
            float2 v1{acc[mt][nt][2] * scale, acc[mt][nt][3] * scale};
            if (epi == 1) {
                __nv_bfloat16 h0, l0, h1, l1;
                split1(v0.x, h0, l0); split1(v0.y, h1, l1);
                *(__nv_bfloat162*)(Chi + i0) = __nv_bfloat162{h0, h1};
                *(__nv_bfloat162*)(Clo + i0) = __nv_bfloat162{l0, l1};
                split1(v1.x, h0, l0); split1(v1.y, h1, l1);
                *(__nv_bfloat162*)(Chi + i1) = __nv_bfloat162{h0, h1};
                *(__nv_bfloat162*)(Clo + i1) = __nv_bfloat162{l0, l1};
            } else {
                if (epi == 2) {
                    v0.x += addP[i0]; v0.y += addP[i0 + 1];
                    v1.x += addP[i1]; v1.y += addP[i1 + 1];
                }
                *(float2*)(C + i0) = v0;
                *(float2*)(C + i1) = v1;
            }
        }
    }
}

// ---------------------------------------------------------------------------
extern "C" void kernel_launch(void* const* d_in, const int* in_sizes, int n_in,
                              void* d_out, int out_size) {
    const float* zq = (const float*)d_in[0];
    const float* zs = (const float*)d_in[1];
    const float* zv = (const float*)d_in[2];
    const float* cf = (const float*)d_in[3];
    const float* Wk = (const float*)d_in[4];
    const float* Wv = (const float*)d_in[5];
    const float* Wo = (const float*)d_in[6];
    const float* mem = (const float*)d_in[7];

    float* out = (float*)d_out;
    float* vret = out;
    float* newmem = out + (long)Bn * Dn;

    float* pT;
    cudaGetSymbolAddress((void**)&pT, g_T);

#define SYM(p, s) __nv_bfloat16* p; cudaGetSymbolAddress((void**)&p, s)
    SYM(pWk_h, sWk_h);   SYM(pWk_l, sWk_l);
    SYM(pWkT_h, sWkT_h); SYM(pWkT_l, sWkT_l);
    SYM(pMemT_h, sMemT_h); SYM(pMemT_l, sMemT_l);
    SYM(pWvT_h, sWvT_h); SYM(pWvT_l, sWvT_l);
    SYM(pWoT_h, sWoT_h); SYM(pWoT_l, sWoT_l);
    SYM(pZq_h, sZq_h);   SYM(pZq_l, sZq_l);
    SYM(pZsT_h, sZsT_h); SYM(pZsT_l, sZsT_l);
    SYM(pZvT_h, sZvT_h); SYM(pZvT_l, sZvT_l);
    SYM(pA1_h, sA1_h);   SYM(pA1_l, sA1_l);
    SYM(pA2T_h, sA2T_h); SYM(pA2T_l, sA2T_l);
    SYM(pST_h, sST_h);   SYM(pST_l, sST_l);
    SYM(pT_h, sT_h);     SYM(pT_l, sT_l);
#undef SYM

    cudaFuncSetAttribute(mma_dual, cudaFuncAttributeMaxDynamicSharedMemorySize, GSMEM);

    // --- forked conversion phase (parallel branches in the captured graph) ---
    cudaStream_t st[4];
    cudaEvent_t evFork, evJoin[4], evFork2, evJoin2;
    for (int i = 0; i < 4; i++) cudaStreamCreateWithFlags(&st[i], cudaStreamNonBlocking);
    cudaEventCreateWithFlags(&evFork, cudaEventDisableTiming);
    cudaEventCreateWithFlags(&evFork2, cudaEventDisableTiming);
    cudaEventCreateWithFlags(&evJoin2, cudaEventDisableTiming);
    for (int i = 0; i < 4; i++) cudaEventCreateWithFlags(&evJoin[i], cudaEventDisableTiming);

    cudaEventRecord(evFork, 0);
    for (int i = 0; i < 4; i++) cudaStreamWaitEvent(st[i], evFork, 0);

    convWk4<<<dim3(128, 8), 256, 0, st[0]>>>(Wk, pWk_h, pWk_l, pWkT_h, pWkT_l);
    transSplit4<<<dim3(8, 128), 256, 0, st[1]>>>(mem, pMemT_h, pMemT_l, 8192, 512);
    transSplit4<<<dim3(128, 8), 256, 0, st[2]>>>(Wv, pWvT_h, pWvT_l, 512, 8192);
    transSplit4<<<dim3(8, 8), 256, 0, st[2]>>>(Wo, pWoT_h, pWoT_l, 512, 512);
    prep_lam_kernel<<<1, 256, 0, st[3]>>>(cf);
    convZ4<<<dim3(8, 64), 256, 0, st[3]>>>(zq, zs, zv, pZq_h, pZq_l,
                                           pZsT_h, pZsT_l, pZvT_h, pZvT_l);

    for (int i = 0; i < 4; i++) {
        cudaEventRecord(evJoin[i], st[i]);
        cudaStreamWaitEvent(0, evJoin[i], 0);
    }

    auto mkop = [](const __nv_bfloat16* Ah, const __nv_bfloat16* Al,
                   const __nv_bfloat16* Bh, const __nv_bfloat16* Bl,
                   float* C, __nv_bfloat16* Chi, __nv_bfloat16* Clo, const float* addC,
                   int K, int ldA, int ldB, int ldC, int ksplit, int epi,
                   int gx, int gy, int gz, long sA, long sB, long sC, long sAdd,
                   long sSplit, float alpha) {
        GOp o;
        o.Ah = Ah; o.Al = Al; o.Bh = Bh; o.Bl = Bl;
        o.C = C; o.Chi = Chi; o.Clo = Clo; o.addC = addC;
        o.K = K; o.ldA = ldA; o.ldB = ldB; o.ldC = ldC;
        o.ksplit = ksplit; o.epi = epi; o.gx = gx; o.gy = gy;
        o.ctaCount = gx * gy * gz;
        o.sA = sA; o.sB = sB; o.sC = sC; o.sAdd = sAdd; o.sSplit = sSplit;
        o.alpha = alpha;
        return o;
    };

    // G1: s1 (A1 partials, K=8192 ksplit 8) + s4 (S partials, K=4096 ksplit 8)
    GOp s1 = mkop(pWk_h, pWk_l, pMemT_h, pMemT_l, pT, nullptr, nullptr, nullptr,
                  8192, 8192, 8192, 512, 8, 0, 4, 4, 8, 0, 0, 0, 0, DD, 1.f);
    GOp s4 = mkop(pZsT_h, pZsT_l, pZvT_h, pZvT_l, pT + 8 * DD, nullptr, nullptr, nullptr,
                  4096, 4096, 4096, 512, 8, 0, 4, 4, 8, 0, 0, 0, 0, DD, 1.f);
    mma_dual<<<s1.ctaCount + s4.ctaCount, 256, GSMEM>>>(s1, s4);

    // forked reduces (independent of each other)
    cudaEventRecord(evFork2, 0);
    cudaStreamWaitEvent(st[0], evFork2, 0);
    reduce_split<<<(Dn * Dn + 255) / 256, 256, 0, st[0]>>>(pT, pA1_h, pA1_l, Dn * Dn, 8);
    reduce_splitT<<<dim3(16, 16), dim3(32, 8)>>>(pT + 8 * DD, pST_h, pST_l, 8);
    cudaEventRecord(evJoin2, st[0]);
    cudaStreamWaitEvent(0, evJoin2, 0);

    // G2: s5 (T_h, bf16 epilogue) + s2 (A2 partials)
    GOp s5 = mkop(pWkT_h, pWkT_l, pST_h, pST_l, nullptr, pT_h, pT_l, nullptr,
                  512, 512, 512, 512, 1, 1, 4, 4, 16, DD, 0, DD, 0, 0, 1.f);
    GOp s2 = mkop(pA1_h, pA1_l, pWoT_h, pWoT_l, pT, nullptr, nullptr, nullptr,
                  512, 512, 512, 512, 4, 0, 4, 4, 4, 0, 0, 0, 0, DD, 1.f / Hn);
    mma_dual<<<s5.ctaCount + s2.ctaCount, 256, GSMEM>>>(s5, s2);

    reduce_splitT<<<dim3(16, 16), dim3(32, 8)>>>(pT, pA2T_h, pA2T_l, 4);

    // G3: s6 (new_mem) + s3 (v_ret)
    GOp s6 = mkop(pT_h, pT_l, pWvT_h, pWvT_l, newmem, nullptr, nullptr, mem,
                  512, 512, 512, 512, 1, 2, 4, 4, 16, DD, DD, DD, DD, 0, 1.f);
    GOp s3 = mkop(pZq_h, pZq_l, pA2T_h, pA2T_l, vret, nullptr, nullptr, nullptr,
                  512, 512, 512, 512, 1, 0, 4, 32, 1, 0, 0, 0, 0, 0, 1.f);
    mma_dual<<<s6.ctaCount + s3.ctaCount, 256, GSMEM>>>(s6, s3);

    // cleanup host-side objects (no device memory involved)
    for (int i = 0; i < 4; i++) cudaStreamDestroy(st[i]);
    cudaEventDestroy(evFork); cudaEventDestroy(evFork2); cudaEventDestroy(evJoin2);
    for (int i = 0; i < 4; i++) cudaEventDestroy(evJoin[i]);
}